// round 8
// baseline (speedup 1.0000x reference)
#include <cuda_runtime.h>
#include <math.h>

#define BB 2
#define TT 20
#define VV 256
#define PPB (TT*VV)          // 5120 points per batch
#define NPTS (BB*PPB)        // 10240
#define NSPLIT 40
#define QCHUNK (PPB/NSPLIT)  // 128
#define BLKP 128             // threads per k4 CTA
#define PPER 2               // p rows per thread
#define PTILE (BLKP*PPER)    // 256

// ---- device scratch (no allocations allowed) ----
__device__ float4 g_comp2[1024];   // 4-channel 32x32 feature map (atomic-accumulated;
                                   // zeroed at module load, re-zeroed by k5 each run)
__device__ float4 g_Qt[NPTS];      // (Xf0,Xf1,Xf2,Xf3) per p
__device__ float4 g_Kt[NPTS];      // k~ = C_top. w  (4 floats) per q, -log2e folded
__device__ float4 g_Ko[NPTS];      // (off = C_bot.w, 0, x0q, x1q) per q -- (off,0) is a
                                   // ready-made packed f32x2 operand
__device__ float4 g_part[NSPLIT*NPTS];  // (sum_sig, sum_sig*x0, sum_sig*x1, 0)

// ---- packed f32x2 + MUFU helpers ----
__device__ __forceinline__ unsigned long long pk2(float lo, float hi) {
    unsigned long long r;
    asm("mov.b64 %0, {%1, %2};" : "=l"(r) : "f"(lo), "f"(hi));
    return r;
}
__device__ __forceinline__ void upk2(unsigned long long v, float& lo, float& hi) {
    asm("mov.b64 {%0, %1}, %2;" : "=f"(lo), "=f"(hi) : "l"(v));
}
__device__ __forceinline__ unsigned long long fma2(unsigned long long a, unsigned long long b,
                                                   unsigned long long c) {
    unsigned long long r;
    asm("fma.rn.f32x2 %0, %1, %2, %3;" : "=l"(r) : "l"(a), "l"(b), "l"(c));
    return r;
}
__device__ __forceinline__ float ex2f(float x) {
    float r; asm("ex2.approx.f32 %0, %1;" : "=f"(r) : "f"(x)); return r;
}
__device__ __forceinline__ float rcpf(float x) {
    float r; asm("rcp.approx.f32 %0, %1;" : "=f"(r) : "f"(x)); return r;
}
#define NLOG2E (-1.4426950408889634f)
__device__ __forceinline__ float fast_sigmoid(float s) {      // 1/(1+e^-s), err ~1e-6
    return rcpf(1.f + ex2f(NLOG2E * s));
}
__device__ __forceinline__ float fast_tanh(float x) {          // (t-1)/(t+1), t=e^{2x}
    float t = ex2f(2.8853900817779268f * x);                   // 2*log2(e)
    float r = rcpf(t + 1.f);
    return (t - 1.f) * r;
}

// ---------------------------------------------------------------------------
// k2: fused (old k1+k2). Each block stages its 64-channel slice of
// Wsmall = W_fuse[:,4:] @ W_comp in smem, then accumulates comp2 via atomics.
// grid: (8 px-tiles, 32 c-chunks) x 128
// ---------------------------------------------------------------------------
__global__ void k2_comp2(const float* __restrict__ W_fuse,
                         const float* __restrict__ W_comp,
                         const float* __restrict__ b_comp,
                         const float* __restrict__ meta) {
    __shared__ float  sWf[4 * 256];
    __shared__ float4 sWs[64];
    __shared__ float  sBias[4];
    int tid = threadIdx.x;
    int c0 = blockIdx.y * 64;

#pragma unroll
    for (int i = tid; i < 1024; i += 128)
        sWf[i] = W_fuse[(i >> 8) * 260 + 4 + (i & 255)];
    __syncthreads();

    // stage Wsmall[c_local][j]: thread (cl, j0) computes j0 and j0+2
    {
        int cl = tid & 63;
        int j0 = tid >> 6;                 // 0 or 1
        float a0 = 0.f, a1 = 0.f;
        const float* wc = W_comp + c0 + cl;
#pragma unroll 16
        for (int cc = 0; cc < 256; cc++) {
            float w = wc[cc * 2048];
            a0 = fmaf(sWf[j0 * 256 + cc], w, a0);
            a1 = fmaf(sWf[(j0 + 2) * 256 + cc], w, a1);
        }
        ((float*)&sWs[cl])[j0] = a0;
        ((float*)&sWs[cl])[j0 + 2] = a1;
    }

    if (blockIdx.y == 0) {                 // bias fold, once per px-tile (y==0 blocks)
        int j = tid >> 5, lane = tid & 31;
        float s = 0.f;
#pragma unroll
        for (int cc = lane; cc < 256; cc += 32)
            s += sWf[j * 256 + cc] * b_comp[cc];
#pragma unroll
        for (int o = 16; o > 0; o >>= 1)
            s += __shfl_down_sync(0xffffffffu, s, o);
        if (lane == 0) sBias[j] = s;
    }
    __syncthreads();

    int px = blockIdx.x * 128 + tid;       // 0..1023
    float a0 = 0.f, a1 = 0.f, a2 = 0.f, a3 = 0.f;
#pragma unroll 16
    for (int ci = 0; ci < 64; ci++) {
        float m = meta[(c0 + ci) * 1024 + px];
        float4 w = sWs[ci];
        a0 = fmaf(w.x, m, a0);
        a1 = fmaf(w.y, m, a1);
        a2 = fmaf(w.z, m, a2);
        a3 = fmaf(w.w, m, a3);
    }
    if (blockIdx.y == 0) {
        a0 += sBias[0]; a1 += sBias[1]; a2 += sBias[2]; a3 += sBias[3];
    }
    float* dst = (float*)&g_comp2[px];
    atomicAdd(dst + 0, a0);
    atomicAdd(dst + 1, a1);
    atomicAdd(dst + 2, a2);
    atomicAdd(dst + 3, a3);
}

// ---------------------------------------------------------------------------
// k3: per-point PE + LSTM + bilinear sample + fuse -> Xf; and the q-side
// subspace projections: k~ = C_top.w, off = C_bot.w with C = A^T B * (-log2e)
// grid: 40 x 256 (one point per thread)
// ---------------------------------------------------------------------------
__global__ void k3_qkv(const float* __restrict__ x, const float* __restrict__ ac,
                       const float* __restrict__ W_ih, const float* __restrict__ b_ih,
                       const float* __restrict__ b_hh,
                       const float* __restrict__ W_fuse, const float* __restrict__ b_fuse,
                       const float* __restrict__ W_fc,  const float* __restrict__ b_fc,
                       const float* __restrict__ W_fc2, const float* __restrict__ b_fc2) {
    int p = blockIdx.x * 256 + threadIdx.x;
    if (p >= NPTS) return;
    int b = p / PPB, r = p % PPB, t = r / VV, v = r % VV;

    // C[i][j] = sum_d A[d][i]*B[d][j], scaled by -log2e
    // A[d][i] = W_fc[d][i] (i<4), b_fc[d] (i=4); B[d][j] = W_fc2[d][j] (j<2), b_fc2[d] (j=2)
    float C[5][3];
#pragma unroll
    for (int i = 0; i < 5; i++)
#pragma unroll
        for (int j = 0; j < 3; j++) {
            float s = 0.f;
#pragma unroll
            for (int d = 0; d < 8; d++) {
                float av = (i < 4) ? W_fc[d * 4 + i] : b_fc[d];
                float bv = (j < 2) ? W_fc2[d * 2 + j] : b_fc2[d];
                s = fmaf(av, bv, s);
            }
            C[i][j] = NLOG2E * s;
        }

    // positional encoding: c=2 -> pe = (sin t, cos t)
    float x0 = x[((b * TT + t) * VV + v) * 2 + 0] + __sinf((float)t);
    float x1 = x[((b * TT + t) * VV + v) * 2 + 1] + __cosf((float)t);

    // q-side: k~, off (packed-ready layout), and raw w for the V expansion in k5
    {
        float kt0 = fmaf(C[0][0], x0, fmaf(C[0][1], x1, C[0][2]));
        float kt1 = fmaf(C[1][0], x0, fmaf(C[1][1], x1, C[1][2]));
        float kt2 = fmaf(C[2][0], x0, fmaf(C[2][1], x1, C[2][2]));
        float kt3 = fmaf(C[3][0], x0, fmaf(C[3][1], x1, C[3][2]));
        float off = fmaf(C[4][0], x0, fmaf(C[4][1], x1, C[4][2]));
        g_Kt[p] = make_float4(kt0, kt1, kt2, kt3);
        g_Ko[p] = make_float4(off, 0.f, x0, x1);
    }

    // single-step LSTM (h0=c0=0), gate order i,f,g,o (f unused since c0=0)
    float h[4];
#pragma unroll
    for (int j = 0; j < 4; j++) {
        float gi = fmaf(x0, W_ih[(0 + j) * 2 + 0], fmaf(x1, W_ih[(0 + j) * 2 + 1],
                        b_ih[0 + j] + b_hh[0 + j]));
        float gg = fmaf(x0, W_ih[(8 + j) * 2 + 0], fmaf(x1, W_ih[(8 + j) * 2 + 1],
                        b_ih[8 + j] + b_hh[8 + j]));
        float go = fmaf(x0, W_ih[(12 + j) * 2 + 0], fmaf(x1, W_ih[(12 + j) * 2 + 1],
                        b_ih[12 + j] + b_hh[12 + j]));
        float cst = fast_sigmoid(gi) * fast_tanh(gg);
        h[j] = fast_sigmoid(go) * fast_tanh(cst);
    }

    // bilinear grid sample on folded 4-ch map (align_corners=False, zero pad)
    float cx = ac[((b * 2 + 0) * TT + t) * VV + v];
    float cy = ac[((b * 2 + 1) * TT + t) * VV + v];
    float fx = cx * (1.f / 16.f) - 0.5f;
    float fy = cy * (1.f / 16.f) - 0.5f;
    float x0f = floorf(fx), y0f = floorf(fy);
    int ix0 = (int)x0f, iy0 = (int)y0f;
    float wx1 = fx - x0f, wx0 = 1.f - wx1;
    float wy1 = fy - y0f, wy0 = 1.f - wy1;
    float l0 = 0.f, l1 = 0.f, l2 = 0.f, l3 = 0.f;
#pragma unroll
    for (int dy = 0; dy < 2; dy++) {
#pragma unroll
        for (int dx = 0; dx < 2; dx++) {
            int xx = ix0 + dx, yy = iy0 + dy;
            if (xx >= 0 && xx < 32 && yy >= 0 && yy < 32) {
                float w = (dx ? wx1 : wx0) * (dy ? wy1 : wy0);
                float4 cv = g_comp2[yy * 32 + xx];
                l0 = fmaf(w, cv.x, l0);
                l1 = fmaf(w, cv.y, l1);
                l2 = fmaf(w, cv.z, l2);
                l3 = fmaf(w, cv.w, l3);
            }
        }
    }

    // fuse: Xf = W_fuse[:, :4] @ h + local + b_fuse
    float Xf[4] = {l0, l1, l2, l3};
#pragma unroll
    for (int j = 0; j < 4; j++) {
        float s = Xf[j] + b_fuse[j];
#pragma unroll
        for (int k = 0; k < 4; k++) s = fmaf(W_fuse[j * 260 + k], h[k], s);
        Xf[j] = s;
    }
    g_Qt[p] = make_float4(Xf[0], Xf[1], Xf[2], Xf[3]);
}

// ---------------------------------------------------------------------------
// k4: attention partials in the subspace form.
// s' = Xf_p . k~_q + off_q  (already -log2e scaled); sig = rcp(1+ex2(s'))
// accumulate (sig, sig*x0q, sig*x1q)
// grid: (20 p-tiles, 40 q-chunks, B) x 128; 2 p-rows per thread
// ---------------------------------------------------------------------------
__global__ void __launch_bounds__(BLKP) k4_attn() {
    int tid = threadIdx.x;
    int b = blockIdx.z;
    int split = blockIdx.y;
    int p0 = blockIdx.x * PTILE + tid;       // p1 = p0 + BLKP
    int pg0 = b * PPB + p0;
    int pg1 = pg0 + BLKP;

    __shared__ float4 sKt[QCHUNK];
    __shared__ float4 sKo[QCHUNK];           // (off, 0, x0, x1)

    int qbase = b * PPB + split * QCHUNK;
    sKt[tid] = g_Kt[qbase + tid];            // BLKP == QCHUNK
    sKo[tid] = g_Ko[qbase + tid];

    float4 xf0f = g_Qt[pg0];
    float4 xf1f = g_Qt[pg1];
    ulonglong2 X0 = *reinterpret_cast<ulonglong2*>(&xf0f);   // (Xf0,Xf1) (Xf2,Xf3)
    ulonglong2 X1 = *reinterpret_cast<ulonglong2*>(&xf1f);

    float aS0 = 0.f, aW00 = 0.f, aW10 = 0.f;
    float aS1 = 0.f, aW01 = 0.f, aW11 = 0.f;

    __syncthreads();

#pragma unroll 4
    for (int j = 0; j < QCHUNK; j++) {
        float4 ktf = sKt[j];
        ulonglong2 kt = *reinterpret_cast<ulonglong2*>(&ktf);
        float4 kof = sKo[j];
        ulonglong2 ko = *reinterpret_cast<ulonglong2*>(&kof);  // .x = (off,0) packed

        unsigned long long d0 = fma2(X0.x, kt.x, ko.x);
        d0 = fma2(X0.y, kt.y, d0);
        unsigned long long d1 = fma2(X1.x, kt.x, ko.x);
        d1 = fma2(X1.y, kt.y, d1);

        float lo, hi;
        upk2(d0, lo, hi);
        float s0 = lo + hi;
        upk2(d1, lo, hi);
        float s1 = lo + hi;

        float sg0 = rcpf(1.f + ex2f(s0));
        float sg1 = rcpf(1.f + ex2f(s1));

        aS0 += sg0;
        aW00 = fmaf(sg0, kof.z, aW00);
        aW10 = fmaf(sg0, kof.w, aW10);
        aS1 += sg1;
        aW01 = fmaf(sg1, kof.z, aW01);
        aW11 = fmaf(sg1, kof.w, aW11);
    }

    int oi = (split * BB + b) * PPB + p0;
    g_part[oi] = make_float4(aS0, aW00, aW10, 0.f);
    g_part[oi + BLKP] = make_float4(aS1, aW01, aW11, 0.f);
}

// ---------------------------------------------------------------------------
// k5: reduce 3-vector partials, expand via [W_fc3|b_fc3], threshold,
// project 8->5, write transposed (b, 5, t, n). Also re-zero g_comp2.
// grid: 40 x 256
// ---------------------------------------------------------------------------
__global__ void k5_final(const float* __restrict__ W_fc3, const float* __restrict__ b_fc3,
                         const float* __restrict__ W_out, const float* __restrict__ b_out,
                         float* __restrict__ out) {
    int p = blockIdx.x * 256 + threadIdx.x;
    if (p >= NPTS) return;
    int b = p / PPB, r = p % PPB, t = r / VV, v = r % VV;

    float S = 0.f, W0 = 0.f, W1 = 0.f;
#pragma unroll 8
    for (int s = 0; s < NSPLIT; s++) {
        float4 a = g_part[(s * BB + b) * PPB + r];
        S += a.x; W0 += a.y; W1 += a.z;
    }

    float o[8];
#pragma unroll
    for (int d = 0; d < 8; d++) {
        float y = fmaf(W_fc3[d * 2 + 0], W0, fmaf(W_fc3[d * 2 + 1], W1, b_fc3[d] * S));
        o[d] = (y > 0.5f) ? y : 0.f;
    }
#pragma unroll
    for (int dd = 0; dd < 5; dd++) {
        float y = b_out[dd];
#pragma unroll
        for (int d = 0; d < 8; d++) y = fmaf(W_out[dd * 8 + d], o[d], y);
        out[((b * 5 + dd) * TT + t) * VV + v] = y;
    }

    // re-zero the atomic accumulator for the next graph replay
    if (p < 1024) g_comp2[p] = make_float4(0.f, 0.f, 0.f, 0.f);
}

// ---------------------------------------------------------------------------
extern "C" void kernel_launch(void* const* d_in, const int* in_sizes, int n_in,
                              void* d_out, int out_size) {
    const float* x      = (const float*)d_in[0];
    const float* ac     = (const float*)d_in[1];
    const float* meta   = (const float*)d_in[2];
    const float* W_ih   = (const float*)d_in[3];
    // d_in[4] = W_hh (unused: h0 = 0)
    const float* b_ih   = (const float*)d_in[5];
    const float* b_hh   = (const float*)d_in[6];
    const float* W_comp = (const float*)d_in[7];
    const float* b_comp = (const float*)d_in[8];
    const float* W_fuse = (const float*)d_in[9];
    const float* b_fuse = (const float*)d_in[10];
    const float* W_fc   = (const float*)d_in[11];
    const float* b_fc   = (const float*)d_in[12];
    const float* W_fc2  = (const float*)d_in[13];
    const float* b_fc2  = (const float*)d_in[14];
    const float* W_fc3  = (const float*)d_in[15];
    const float* b_fc3  = (const float*)d_in[16];
    const float* W_out  = (const float*)d_in[17];
    const float* b_out  = (const float*)d_in[18];
    float* out = (float*)d_out;

    k2_comp2<<<dim3(8, 32), 128>>>(W_fuse, W_comp, b_comp, meta);
    k3_qkv<<<40, 256>>>(x, ac, W_ih, b_ih, b_hh, W_fuse, b_fuse,
                        W_fc, b_fc, W_fc2, b_fc2);
    k4_attn<<<dim3(PPB / PTILE, NSPLIT, BB), BLKP>>>();
    k5_final<<<40, 256>>>(W_fc3, b_fc3, W_out, b_out, out);
}